// round 1
// baseline (speedup 1.0000x reference)
#include <cuda_runtime.h>
#include <cuda_bf16.h>
#include <math.h>

// ---------------------------------------------------------------------------
// MLA prefill pipeline, fp32 baseline (Round 1: correctness + analyzable SOL)
//   B=2, S=2048, D=2048, H=16, dh=128
//   out  = [B,S,D] @ d_out[0 .. 8388608)
//   ckv  = [B,S,D] @ d_out[8388608 .. 16777216)
// ---------------------------------------------------------------------------

#define D_MODEL 2048
#define SEQ     2048
#define BATCH   2
#define NHEADS  16
#define DH      128
#define ROWS    (BATCH * SEQ)          // 4096
#define OUT_HALF ((size_t)ROWS * D_MODEL)  // 8388608

// ----------------------------- scratch (static, no allocs) ------------------
__device__ float g_t0[(size_t)ROWS * D_MODEL];        // 32 MB  pre-LN buffer
__device__ float g_cq[(size_t)ROWS * D_MODEL];        // 32 MB
__device__ float g_Q [(size_t)ROWS * D_MODEL];        // 32 MB
__device__ float g_KV[(size_t)ROWS * 2 * D_MODEL];    // 64 MB  [K | V]
__device__ float g_O [(size_t)ROWS * D_MODEL];        // 32 MB
__device__ float g_cos[SEQ][DH / 2];
__device__ float g_sin[SEQ][DH / 2];

// ----------------------------- SGEMM 128x128x8 ------------------------------
// C[M,N] = A[M,K] @ B            (TRANSB=false, B row-major [K,N])
// C[M,N] = A[M,K] @ B^T          (TRANSB=true,  B row-major [N,K])
template <bool TRANSB>
__global__ __launch_bounds__(256) void sgemm128(
    const float* __restrict__ A, const float* __restrict__ B,
    float* __restrict__ C, int M, int N, int K)
{
    __shared__ float As[8][128];
    __shared__ float Bs[8][128];
    const int tid = threadIdx.x;
    const int tr  = tid >> 4;            // 0..15
    const int tc  = tid & 15;            // 0..15
    const int ldr = tid >> 1;            // 0..127 (row within 128-row tile)
    const int ldc = (tid & 1) << 2;      // 0 or 4 (float4 within 8-wide K slab)
    const int brow = tid >> 5;           // 0..7   (NN B-tile load)
    const int bcol = (tid & 31) << 2;    // 0..124

    const float* Ab = A + (size_t)blockIdx.y * 128 * K;

    float acc[8][8];
#pragma unroll
    for (int i = 0; i < 8; i++)
#pragma unroll
        for (int j = 0; j < 8; j++) acc[i][j] = 0.f;

    for (int k0 = 0; k0 < K; k0 += 8) {
        float4 av = *reinterpret_cast<const float4*>(Ab + (size_t)ldr * K + k0 + ldc);
        As[ldc + 0][ldr] = av.x; As[ldc + 1][ldr] = av.y;
        As[ldc + 2][ldr] = av.z; As[ldc + 3][ldr] = av.w;
        if (TRANSB) {
            const float* Bb = B + (size_t)blockIdx.x * 128 * K;
            float4 bv = *reinterpret_cast<const float4*>(Bb + (size_t)ldr * K + k0 + ldc);
            Bs[ldc + 0][ldr] = bv.x; Bs[ldc + 1][ldr] = bv.y;
            Bs[ldc + 2][ldr] = bv.z; Bs[ldc + 3][ldr] = bv.w;
        } else {
            float4 bv = *reinterpret_cast<const float4*>(
                B + (size_t)(k0 + brow) * N + blockIdx.x * 128 + bcol);
            *reinterpret_cast<float4*>(&Bs[brow][bcol]) = bv;
        }
        __syncthreads();
#pragma unroll
        for (int k = 0; k < 8; k++) {
            float rA[8], rB[8];
            *reinterpret_cast<float4*>(&rA[0]) = *reinterpret_cast<float4*>(&As[k][tr * 8]);
            *reinterpret_cast<float4*>(&rA[4]) = *reinterpret_cast<float4*>(&As[k][tr * 8 + 4]);
            *reinterpret_cast<float4*>(&rB[0]) = *reinterpret_cast<float4*>(&Bs[k][tc * 8]);
            *reinterpret_cast<float4*>(&rB[4]) = *reinterpret_cast<float4*>(&Bs[k][tc * 8 + 4]);
#pragma unroll
            for (int i = 0; i < 8; i++)
#pragma unroll
                for (int j = 0; j < 8; j++) acc[i][j] += rA[i] * rB[j];
        }
        __syncthreads();
    }

    float* Cb = C + (size_t)(blockIdx.y * 128 + tr * 8) * N + blockIdx.x * 128 + tc * 8;
#pragma unroll
    for (int i = 0; i < 8; i++) {
        *reinterpret_cast<float4*>(Cb + (size_t)i * N) =
            make_float4(acc[i][0], acc[i][1], acc[i][2], acc[i][3]);
        *reinterpret_cast<float4*>(Cb + (size_t)i * N + 4) =
            make_float4(acc[i][4], acc[i][5], acc[i][6], acc[i][7]);
    }
}

// ----------------------------- LayerNorm per row ----------------------------
__global__ __launch_bounds__(256) void layernorm_rows(
    const float* __restrict__ in, const float* __restrict__ gamma,
    const float* __restrict__ beta, float* __restrict__ out)
{
    __shared__ float red[16];
    const int row = blockIdx.x;
    const float* x = in + (size_t)row * D_MODEL;
    float s = 0.f, s2 = 0.f;
    for (int i = threadIdx.x; i < D_MODEL; i += 256) {
        float v = x[i]; s += v; s2 += v * v;
    }
#pragma unroll
    for (int o = 16; o; o >>= 1) {
        s  += __shfl_xor_sync(0xffffffffu, s,  o);
        s2 += __shfl_xor_sync(0xffffffffu, s2, o);
    }
    const int wid = threadIdx.x >> 5, lane = threadIdx.x & 31;
    if (lane == 0) { red[wid] = s; red[wid + 8] = s2; }
    __syncthreads();
    if (threadIdx.x < 32) {
        s  = (lane < 8) ? red[lane]     : 0.f;
        s2 = (lane < 8) ? red[lane + 8] : 0.f;
#pragma unroll
        for (int o = 4; o; o >>= 1) {
            s  += __shfl_xor_sync(0xffffffffu, s,  o);
            s2 += __shfl_xor_sync(0xffffffffu, s2, o);
        }
        if (lane == 0) { red[0] = s; red[1] = s2; }
    }
    __syncthreads();
    const float mean = red[0] * (1.f / D_MODEL);
    const float var  = red[1] * (1.f / D_MODEL) - mean * mean;
    const float rstd = rsqrtf(var + 1e-5f);
    float* o_ = out + (size_t)row * D_MODEL;
    for (int i = threadIdx.x; i < D_MODEL; i += 256)
        o_[i] = (x[i] - mean) * rstd * gamma[i] + beta[i];
}

// ----------------------------- RoPE tables (double precision) ---------------
__global__ void rope_table()
{
    const int s = blockIdx.x;          // 0..2047
    const int i = threadIdx.x;         // 0..63
    const double freq = pow(10000.0, -2.0 * (double)i / (double)DH);
    const double a = (double)s * freq;
    g_cos[s][i] = (float)cos(a);
    g_sin[s][i] = (float)sin(a);
}

// ----------------------------- RoPE apply to Q and K (in place) -------------
__global__ __launch_bounds__(256) void rope_apply(float* __restrict__ Q, float* __restrict__ KV)
{
    const int row = blockIdx.x;        // b*S + s
    const int s   = row & (SEQ - 1);
    for (int p = threadIdx.x; p < NHEADS * (DH / 2); p += 256) {
        const int h = p >> 6, i = p & 63;
        const float cs = g_cos[s][i], sn = g_sin[s][i];
        const size_t bq = (size_t)row * D_MODEL + h * DH;
        const float x1 = Q[bq + i], x2 = Q[bq + 64 + i];
        Q[bq + i]      = x1 * cs - x2 * sn;
        Q[bq + 64 + i] = x2 * cs + x1 * sn;
        const size_t bk = (size_t)row * (2 * D_MODEL) + h * DH;
        const float y1 = KV[bk + i], y2 = KV[bk + 64 + i];
        KV[bk + i]      = y1 * cs - y2 * sn;
        KV[bk + 64 + i] = y2 * cs + y1 * sn;
    }
}

// ----------------------------- Flash attention (causal, fp32) ---------------
// grid: (S/64, B*H), block 256.  Thread (r = tid/4, c = tid%4) owns query row
// r of the 64-row block and dims [c*32, c*32+32).  BC=32 keys per tile.
#define BR 64
#define BC 32
__global__ __launch_bounds__(256) void flash_attn(
    const float* __restrict__ Q, const float* __restrict__ KV, float* __restrict__ O)
{
    __shared__ float Ks[BC][DH];
    __shared__ float Vs[BC][DH];
    const int qb  = blockIdx.x;
    const int bh  = blockIdx.y;
    const int b   = bh >> 4, h = bh & 15;
    const int tid = threadIdx.x;
    const int r   = tid >> 2;
    const int c   = tid & 3;
    const int qs  = qb * BR + r;                 // query position in [0,S)
    const float scale = 0.08838834764831845f;    // 1/sqrt(128)

    float q[32], o[32];
    {
        const float* qrow = Q + ((size_t)(b * SEQ + qs)) * D_MODEL + h * DH + c * 32;
#pragma unroll
        for (int d = 0; d < 32; d += 4) {
            float4 v = *reinterpret_cast<const float4*>(qrow + d);
            q[d] = v.x * scale; q[d + 1] = v.y * scale;
            q[d + 2] = v.z * scale; q[d + 3] = v.w * scale;
        }
    }
#pragma unroll
    for (int d = 0; d < 32; d++) o[d] = 0.f;

    float m = -1e30f, l = 0.f;
    const int ktiles = 2 * qb + 2;               // keys up to qb*64+63

    for (int kt = 0; kt < ktiles; kt++) {
        // load K,V tiles: 32 rows x 128 floats each; 4 float4 per thread per tile
#pragma unroll
        for (int ld = 0; ld < 4; ld++) {
            const int e    = tid + ld * 256;     // float4 index 0..1023
            const int krow = e >> 5;             // /32 float4-per-row
            const int col4 = (e & 31) << 2;
            const int ks   = kt * BC + krow;
            const float* kvb = KV + ((size_t)(b * SEQ + ks)) * (2 * D_MODEL) + h * DH;
            *reinterpret_cast<float4*>(&Ks[krow][col4]) =
                *reinterpret_cast<const float4*>(kvb + col4);
            *reinterpret_cast<float4*>(&Vs[krow][col4]) =
                *reinterpret_cast<const float4*>(kvb + D_MODEL + col4);
        }
        __syncthreads();

        float s[BC];
#pragma unroll
        for (int j = 0; j < BC; j++) {
            float a = 0.f;
#pragma unroll
            for (int d = 0; d < 32; d++) a += q[d] * Ks[j][c * 32 + d];
            s[j] = a;
        }
        // sum partial dots across the 4 threads of this row (lanes differ in bits 0..1)
#pragma unroll
        for (int j = 0; j < BC; j++) {
            s[j] += __shfl_xor_sync(0xffffffffu, s[j], 1);
            s[j] += __shfl_xor_sync(0xffffffffu, s[j], 2);
        }
        // causal mask (only the last two tiles can be partial)
        if (kt * BC + BC - 1 > qs) {
#pragma unroll
            for (int j = 0; j < BC; j++)
                if (kt * BC + j > qs) s[j] = -1e30f;
        }
        // online softmax
        float mt = m;
#pragma unroll
        for (int j = 0; j < BC; j++) mt = fmaxf(mt, s[j]);
        const float alpha = expf(m - mt);
        float psum = 0.f;
#pragma unroll
        for (int j = 0; j < BC; j++) { s[j] = expf(s[j] - mt); psum += s[j]; }
        l = l * alpha + psum;
        m = mt;
#pragma unroll
        for (int d = 0; d < 32; d++) o[d] *= alpha;
#pragma unroll
        for (int j = 0; j < BC; j++)
#pragma unroll
            for (int d = 0; d < 32; d++) o[d] += s[j] * Vs[j][c * 32 + d];
        __syncthreads();
    }

    const float inv = 1.f / l;
    float* orow = O + ((size_t)(b * SEQ + qs)) * D_MODEL + h * DH + c * 32;
#pragma unroll
    for (int d = 0; d < 32; d += 4) {
        float4 v = make_float4(o[d] * inv, o[d + 1] * inv, o[d + 2] * inv, o[d + 3] * inv);
        *reinterpret_cast<float4*>(orow + d) = v;
    }
}

// ----------------------------- launch ----------------------------------------
extern "C" void kernel_launch(void* const* d_in, const int* in_sizes, int n_in,
                              void* d_out, int out_size)
{
    const float* x       = (const float*)d_in[0];
    const float* W_dq    = (const float*)d_in[1];
    const float* W_uq    = (const float*)d_in[2];
    const float* q_gamma = (const float*)d_in[3];
    const float* q_beta  = (const float*)d_in[4];
    const float* W_dkv   = (const float*)d_in[5];
    const float* W_ukv   = (const float*)d_in[6];
    const float* kv_gamma= (const float*)d_in[7];
    const float* kv_beta = (const float*)d_in[8];
    const float* W_o     = (const float*)d_in[9];

    float* out = (float*)d_out;            // [4096, 2048]
    float* ckv = out + OUT_HALF;           // [4096, 2048]

    float *t0, *cq, *Qp, *KVp, *Op;
    cudaGetSymbolAddress((void**)&t0,  g_t0);
    cudaGetSymbolAddress((void**)&cq,  g_cq);
    cudaGetSymbolAddress((void**)&Qp,  g_Q);
    cudaGetSymbolAddress((void**)&KVp, g_KV);
    cudaGetSymbolAddress((void**)&Op,  g_O);

    const dim3 gN(D_MODEL / 128, ROWS / 128);       // (16, 32)
    const dim3 gKV(2 * D_MODEL / 128, ROWS / 128);  // (32, 32)

    // Q path down-proj + LN
    sgemm128<false><<<gN, 256>>>(x, W_dq, t0, ROWS, D_MODEL, D_MODEL);
    layernorm_rows<<<ROWS, 256>>>(t0, q_gamma, q_beta, cq);
    // KV path down-proj + LN (ckv is an output — write straight into d_out)
    sgemm128<false><<<gN, 256>>>(x, W_dkv, t0, ROWS, D_MODEL, D_MODEL);
    layernorm_rows<<<ROWS, 256>>>(t0, kv_gamma, kv_beta, ckv);
    // up-projections
    sgemm128<false><<<gN, 256>>>(cq, W_uq, Qp, ROWS, D_MODEL, D_MODEL);
    sgemm128<false><<<gKV, 256>>>(ckv, W_ukv, KVp, ROWS, 2 * D_MODEL, D_MODEL);
    // RoPE
    rope_table<<<SEQ, DH / 2>>>();
    rope_apply<<<ROWS, 256>>>(Qp, KVp);
    // causal attention
    flash_attn<<<dim3(SEQ / BR, BATCH * NHEADS), 256>>>(Qp, KVp, Op);
    // output projection: out = O @ W_o^T
    sgemm128<true><<<gN, 256>>>(Op, W_o, out, ROWS, D_MODEL, D_MODEL);
}

// round 3
// speedup vs baseline: 1.3256x; 1.3256x over previous
#include <cuda_runtime.h>
#include <cuda_bf16.h>
#include <math.h>
#include <stdint.h>

// ---------------------------------------------------------------------------
// MLA prefill, Round 3: mma.sync bf16x3 split GEMMs (sm_100-safe PTX)
//   B=2, S=2048, D=2048, H=16, dh=128
//   out = d_out[0..8388608), ckv = d_out[8388608..16777216)
// ---------------------------------------------------------------------------

#define D_MODEL 2048
#define SEQ     2048
#define BATCH   2
#define NHEADS  16
#define DH      128
#define ROWS    (BATCH * SEQ)               // 4096
#define OUT_HALF ((size_t)ROWS * D_MODEL)

typedef __nv_bfloat16 bf16;

// ----------------------------- static scratch -------------------------------
__device__ float g_t0[(size_t)ROWS * D_MODEL];
__device__ float g_Q [(size_t)ROWS * D_MODEL];
__device__ float g_KV[(size_t)ROWS * 2 * D_MODEL];
__device__ float g_cos[SEQ][DH / 2];
__device__ float g_sin[SEQ][DH / 2];

__device__ bf16 g_xh [(size_t)ROWS * D_MODEL], g_xl [(size_t)ROWS * D_MODEL];
__device__ bf16 g_cqh[(size_t)ROWS * D_MODEL], g_cql[(size_t)ROWS * D_MODEL];
__device__ bf16 g_ckvh[(size_t)ROWS * D_MODEL], g_ckvl[(size_t)ROWS * D_MODEL];
__device__ bf16 g_Oh [(size_t)ROWS * D_MODEL], g_Ol [(size_t)ROWS * D_MODEL];
__device__ bf16 g_Wdqh [(size_t)D_MODEL * D_MODEL], g_Wdql [(size_t)D_MODEL * D_MODEL];
__device__ bf16 g_Wdkvh[(size_t)D_MODEL * D_MODEL], g_Wdkvl[(size_t)D_MODEL * D_MODEL];
__device__ bf16 g_Wuqh [(size_t)D_MODEL * D_MODEL], g_Wuql [(size_t)D_MODEL * D_MODEL];
__device__ bf16 g_Wukvh[(size_t)2 * D_MODEL * D_MODEL], g_Wukvl[(size_t)2 * D_MODEL * D_MODEL];
__device__ bf16 g_Woh  [(size_t)D_MODEL * D_MODEL], g_Wol  [(size_t)D_MODEL * D_MODEL];

// ----------------------------- PTX helpers (sm_80-era only) ------------------
__device__ __forceinline__ uint32_t smem_u32(const void* p) {
    uint32_t a;
    asm("{ .reg .u64 t; cvta.to.shared.u64 t, %1; cvt.u32.u64 %0, t; }" : "=r"(a) : "l"(p));
    return a;
}
#define CP_ASYNC16(sa, ga) \
    asm volatile("cp.async.cg.shared.global [%0], [%1], 16;" :: "r"(sa), "l"(ga))
#define CP_COMMIT() asm volatile("cp.async.commit_group;" ::: "memory")
#define CP_WAIT1()  asm volatile("cp.async.wait_group 1;" ::: "memory")
#define CP_WAIT0()  asm volatile("cp.async.wait_group 0;" ::: "memory")
#define LDSM4(r, a) \
    asm volatile("ldmatrix.sync.aligned.m8n8.x4.shared.b16 {%0,%1,%2,%3}, [%4];" \
        : "=r"((r)[0]), "=r"((r)[1]), "=r"((r)[2]), "=r"((r)[3]) : "r"(a))
#define MMA16816(c, a, b) \
    asm volatile("mma.sync.aligned.m16n8k16.row.col.f32.bf16.bf16.f32 " \
        "{%0,%1,%2,%3}, {%4,%5,%6,%7}, {%8,%9}, {%0,%1,%2,%3};" \
        : "+f"((c)[0]), "+f"((c)[1]), "+f"((c)[2]), "+f"((c)[3]) \
        : "r"((a)[0]), "r"((a)[1]), "r"((a)[2]), "r"((a)[3]), "r"((b)[0]), "r"((b)[1]))

// ----------------------------- split kernels ---------------------------------
__global__ __launch_bounds__(256) void split_f32(const float* __restrict__ in,
                                                 bf16* __restrict__ oh, bf16* __restrict__ ol,
                                                 int n4)
{
    int i = blockIdx.x * 256 + threadIdx.x;
    if (i >= n4) return;
    float4 v = reinterpret_cast<const float4*>(in)[i];
    bf16 h0 = __float2bfloat16(v.x), h1 = __float2bfloat16(v.y);
    bf16 h2 = __float2bfloat16(v.z), h3 = __float2bfloat16(v.w);
    reinterpret_cast<__nv_bfloat162*>(oh)[i * 2]     = __halves2bfloat162(h0, h1);
    reinterpret_cast<__nv_bfloat162*>(oh)[i * 2 + 1] = __halves2bfloat162(h2, h3);
    reinterpret_cast<__nv_bfloat162*>(ol)[i * 2] = __halves2bfloat162(
        __float2bfloat16(v.x - __bfloat162float(h0)),
        __float2bfloat16(v.y - __bfloat162float(h1)));
    reinterpret_cast<__nv_bfloat162*>(ol)[i * 2 + 1] = __halves2bfloat162(
        __float2bfloat16(v.z - __bfloat162float(h2)),
        __float2bfloat16(v.w - __bfloat162float(h3)));
}

// transpose + split: out[n*K + k] = W[k*N + n]
__global__ __launch_bounds__(256) void tsplit(const float* __restrict__ W,
                                              bf16* __restrict__ oh, bf16* __restrict__ ol,
                                              int K, int N)
{
    __shared__ float t[32][33];
    const int tx = threadIdx.x, ty = threadIdx.y;
    const int n0 = blockIdx.x * 32, k0 = blockIdx.y * 32;
#pragma unroll
    for (int i = 0; i < 4; i++)
        t[ty + i * 8][tx] = W[(size_t)(k0 + ty + i * 8) * N + n0 + tx];
    __syncthreads();
#pragma unroll
    for (int i = 0; i < 4; i++) {
        float v = t[tx][ty + i * 8];
        int n = n0 + ty + i * 8, k = k0 + tx;
        bf16 h = __float2bfloat16(v);
        oh[(size_t)n * K + k] = h;
        ol[(size_t)n * K + k] = __float2bfloat16(v - __bfloat162float(h));
    }
}

// ----------------------------- mma.sync GEMM ----------------------------------
// C[M,N] fp32 = (Ah+Al)[M,K] @ (Bh+Bl)[N,K]^T   (bf16x3; both K-contiguous)
// 128x128x32 CTA tile, 8 warps (4m x 2n), warp tile 32x64.
// smem: 2 stages x 4 tiles x 8KB = 64KB dynamic.
// swizzle: 16B-chunk index ch' = ch ^ ((row>>1)&3) within a 64B row.
#define GEMM_SMEM 65536

__global__ __launch_bounds__(256) void gemm_mma(
    const bf16* __restrict__ Ah, const bf16* __restrict__ Al,
    const bf16* __restrict__ Bh, const bf16* __restrict__ Bl,
    float* __restrict__ C, int N, int K)
{
    extern __shared__ char sm[];
    const uint32_t smb = smem_u32(sm);
    const int tid  = threadIdx.x;
    const int lane = tid & 31, wid = tid >> 5;
    const int wm = wid & 3, wn = wid >> 2;
    const size_t aB = (size_t)blockIdx.y * 128 * K;
    const size_t bB = (size_t)blockIdx.x * 128 * K;

    float acc[2][8][4];
#pragma unroll
    for (int i = 0; i < 2; i++)
#pragma unroll
        for (int j = 0; j < 8; j++)
#pragma unroll
            for (int t = 0; t < 4; t++) acc[i][j][t] = 0.f;

    auto load_stage = [&](int s, int k0) {
        const uint32_t sb = smb + s * 32768;
#pragma unroll
        for (int h = 0; h < 2; h++) {
            const int c  = tid + h * 256;              // 16B-chunk id 0..511
            const int r  = c >> 2, ch = c & 3;
            const uint32_t off = r * 64 + ((ch ^ ((r >> 1) & 3)) << 4);
            const size_t g = (size_t)r * K + k0 + ch * 8;
            CP_ASYNC16(sb + off,         Ah + aB + g);
            CP_ASYNC16(sb + 8192  + off, Al + aB + g);
            CP_ASYNC16(sb + 16384 + off, Bh + bB + g);
            CP_ASYNC16(sb + 24576 + off, Bl + bB + g);
        }
    };

    auto compute_stage = [&](int s) {
        const uint32_t sb = smb + s * 32768;
#pragma unroll
        for (int kk = 0; kk < 2; kk++) {
            uint32_t ah[2][4], al[2][4];
#pragma unroll
            for (int mt = 0; mt < 2; mt++) {
                const int r     = wm * 32 + mt * 16 + (lane & 15);
                const int chunk = kk * 2 + (lane >> 4);
                const uint32_t off = r * 64 + ((chunk ^ ((r >> 1) & 3)) << 4);
                LDSM4(ah[mt], sb + off);
                LDSM4(al[mt], sb + 8192 + off);
            }
#pragma unroll
            for (int np = 0; np < 4; np++) {
                const int r     = wn * 64 + np * 16 + (lane & 15);
                const int chunk = kk * 2 + (lane >> 4);
                const uint32_t off = r * 64 + ((chunk ^ ((r >> 1) & 3)) << 4);
                uint32_t b4h[4], b4l[4];
                LDSM4(b4h, sb + 16384 + off);
                LDSM4(b4l, sb + 24576 + off);
#pragma unroll
                for (int j = 0; j < 2; j++) {
                    const int nt = np * 2 + j;
                    uint32_t bh2[2] = { b4h[j], b4h[j + 2] };
                    uint32_t bl2[2] = { b4l[j], b4l[j + 2] };
                    MMA16816(acc[0][nt], ah[0], bh2);
                    MMA16816(acc[1][nt], ah[1], bh2);
                    MMA16816(acc[0][nt], ah[0], bl2);
                    MMA16816(acc[1][nt], ah[1], bl2);
                    MMA16816(acc[0][nt], al[0], bh2);
                    MMA16816(acc[1][nt], al[1], bh2);
                }
            }
        }
    };

    load_stage(0, 0);  CP_COMMIT();
    load_stage(1, 32); CP_COMMIT();
    const int iters = K >> 5;
    for (int it = 0; it < iters; it++) {
        const int s = it & 1;
        CP_WAIT1();
        __syncthreads();
        compute_stage(s);
        __syncthreads();
        const int kn = (it + 2) << 5;
        if (kn < K) load_stage(s, kn);
        CP_COMMIT();
    }
    CP_WAIT0();

#pragma unroll
    for (int mt = 0; mt < 2; mt++) {
        const int m0 = blockIdx.y * 128 + wm * 32 + mt * 16 + (lane >> 2);
#pragma unroll
        for (int nt = 0; nt < 8; nt++) {
            const int n = blockIdx.x * 128 + wn * 64 + nt * 8 + (lane & 3) * 2;
            *(float2*)(C + (size_t)m0 * N + n)       = make_float2(acc[mt][nt][0], acc[mt][nt][1]);
            *(float2*)(C + (size_t)(m0 + 8) * N + n) = make_float2(acc[mt][nt][2], acc[mt][nt][3]);
        }
    }
}

// ----------------------------- LayerNorm + split -----------------------------
__global__ __launch_bounds__(256) void layernorm_split(
    const float* __restrict__ in, const float* __restrict__ gamma,
    const float* __restrict__ beta, float* __restrict__ of,
    bf16* __restrict__ oh, bf16* __restrict__ ol)
{
    __shared__ float red[16];
    const int row = blockIdx.x;
    const float* x = in + (size_t)row * D_MODEL;
    float s = 0.f, s2 = 0.f;
    for (int i = threadIdx.x; i < D_MODEL; i += 256) {
        float v = x[i]; s += v; s2 += v * v;
    }
#pragma unroll
    for (int o = 16; o; o >>= 1) {
        s  += __shfl_xor_sync(0xffffffffu, s,  o);
        s2 += __shfl_xor_sync(0xffffffffu, s2, o);
    }
    const int wid = threadIdx.x >> 5, lane = threadIdx.x & 31;
    if (lane == 0) { red[wid] = s; red[wid + 8] = s2; }
    __syncthreads();
    if (threadIdx.x < 32) {
        s  = (lane < 8) ? red[lane]     : 0.f;
        s2 = (lane < 8) ? red[lane + 8] : 0.f;
#pragma unroll
        for (int o = 4; o; o >>= 1) {
            s  += __shfl_xor_sync(0xffffffffu, s,  o);
            s2 += __shfl_xor_sync(0xffffffffu, s2, o);
        }
        if (lane == 0) { red[0] = s; red[1] = s2; }
    }
    __syncthreads();
    const float mean = red[0] * (1.f / D_MODEL);
    const float var  = red[1] * (1.f / D_MODEL) - mean * mean;
    const float rstd = rsqrtf(var + 1e-5f);
    for (int i = threadIdx.x; i < D_MODEL; i += 256) {
        const float v = (x[i] - mean) * rstd * gamma[i] + beta[i];
        if (of) of[(size_t)row * D_MODEL + i] = v;
        const bf16 h = __float2bfloat16(v);
        oh[(size_t)row * D_MODEL + i] = h;
        ol[(size_t)row * D_MODEL + i] = __float2bfloat16(v - __bfloat162float(h));
    }
}

// ----------------------------- RoPE ------------------------------------------
__global__ void rope_table()
{
    const int s = blockIdx.x, i = threadIdx.x;
    const double freq = pow(10000.0, -2.0 * (double)i / (double)DH);
    const double a = (double)s * freq;
    g_cos[s][i] = (float)cos(a);
    g_sin[s][i] = (float)sin(a);
}

__global__ __launch_bounds__(256) void rope_apply(float* __restrict__ Q, float* __restrict__ KV)
{
    const int row = blockIdx.x;
    const int s   = row & (SEQ - 1);
    for (int p = threadIdx.x; p < NHEADS * (DH / 2); p += 256) {
        const int h = p >> 6, i = p & 63;
        const float cs = g_cos[s][i], sn = g_sin[s][i];
        const size_t bq = (size_t)row * D_MODEL + h * DH;
        const float x1 = Q[bq + i], x2 = Q[bq + 64 + i];
        Q[bq + i]      = x1 * cs - x2 * sn;
        Q[bq + 64 + i] = x2 * cs + x1 * sn;
        const size_t bk = (size_t)row * (2 * D_MODEL) + h * DH;
        const float y1 = KV[bk + i], y2 = KV[bk + 64 + i];
        KV[bk + i]      = y1 * cs - y2 * sn;
        KV[bk + 64 + i] = y2 * cs + y1 * sn;
    }
}

// ----------------------------- Flash attention (fp32) -------------------------
#define BR 64
#define BC 32
__global__ __launch_bounds__(256) void flash_attn(
    const float* __restrict__ Q, const float* __restrict__ KV,
    bf16* __restrict__ Oh, bf16* __restrict__ Ol)
{
    __shared__ float Ks[BC][DH];
    __shared__ float Vs[BC][DH];
    const int qb  = blockIdx.x;
    const int bh  = blockIdx.y;
    const int b   = bh >> 4, h = bh & 15;
    const int tid = threadIdx.x;
    const int r   = tid >> 2;
    const int c   = tid & 3;
    const int qs  = qb * BR + r;
    const float scale = 0.08838834764831845f;

    float q[32], o[32];
    {
        const float* qrow = Q + ((size_t)(b * SEQ + qs)) * D_MODEL + h * DH + c * 32;
#pragma unroll
        for (int d = 0; d < 32; d += 4) {
            float4 v = *reinterpret_cast<const float4*>(qrow + d);
            q[d] = v.x * scale; q[d + 1] = v.y * scale;
            q[d + 2] = v.z * scale; q[d + 3] = v.w * scale;
        }
    }
#pragma unroll
    for (int d = 0; d < 32; d++) o[d] = 0.f;

    float m = -1e30f, l = 0.f;
    const int ktiles = 2 * qb + 2;

    for (int kt = 0; kt < ktiles; kt++) {
#pragma unroll
        for (int ld = 0; ld < 4; ld++) {
            const int e    = tid + ld * 256;
            const int krow = e >> 5;
            const int col4 = (e & 31) << 2;
            const int ks   = kt * BC + krow;
            const float* kvb = KV + ((size_t)(b * SEQ + ks)) * (2 * D_MODEL) + h * DH;
            *reinterpret_cast<float4*>(&Ks[krow][col4]) =
                *reinterpret_cast<const float4*>(kvb + col4);
            *reinterpret_cast<float4*>(&Vs[krow][col4]) =
                *reinterpret_cast<const float4*>(kvb + D_MODEL + col4);
        }
        __syncthreads();

        float s[BC];
#pragma unroll
        for (int j = 0; j < BC; j++) {
            float a = 0.f;
#pragma unroll
            for (int d = 0; d < 32; d++) a += q[d] * Ks[j][c * 32 + d];
            s[j] = a;
        }
#pragma unroll
        for (int j = 0; j < BC; j++) {
            s[j] += __shfl_xor_sync(0xffffffffu, s[j], 1);
            s[j] += __shfl_xor_sync(0xffffffffu, s[j], 2);
        }
        if (kt * BC + BC - 1 > qs) {
#pragma unroll
            for (int j = 0; j < BC; j++)
                if (kt * BC + j > qs) s[j] = -1e30f;
        }
        float mt = m;
#pragma unroll
        for (int j = 0; j < BC; j++) mt = fmaxf(mt, s[j]);
        const float alpha = expf(m - mt);
        float psum = 0.f;
#pragma unroll
        for (int j = 0; j < BC; j++) { s[j] = expf(s[j] - mt); psum += s[j]; }
        l = l * alpha + psum;
        m = mt;
#pragma unroll
        for (int d = 0; d < 32; d++) o[d] *= alpha;
#pragma unroll
        for (int j = 0; j < BC; j++)
#pragma unroll
            for (int d = 0; d < 32; d++) o[d] += s[j] * Vs[j][c * 32 + d];
        __syncthreads();
    }

    const float inv = 1.f / l;
    const size_t base = ((size_t)(b * SEQ + qs)) * D_MODEL + h * DH + c * 32;
#pragma unroll
    for (int d = 0; d < 32; d += 2) {
        const float v0 = o[d] * inv, v1 = o[d + 1] * inv;
        const bf16 h0 = __float2bfloat16(v0), h1 = __float2bfloat16(v1);
        reinterpret_cast<__nv_bfloat162*>(Oh + base)[d >> 1] = __halves2bfloat162(h0, h1);
        reinterpret_cast<__nv_bfloat162*>(Ol + base)[d >> 1] = __halves2bfloat162(
            __float2bfloat16(v0 - __bfloat162float(h0)),
            __float2bfloat16(v1 - __bfloat162float(h1)));
    }
}

// ----------------------------- launch ----------------------------------------
extern "C" void kernel_launch(void* const* d_in, const int* in_sizes, int n_in,
                              void* d_out, int out_size)
{
    const float* x       = (const float*)d_in[0];
    const float* W_dq    = (const float*)d_in[1];
    const float* W_uq    = (const float*)d_in[2];
    const float* q_gamma = (const float*)d_in[3];
    const float* q_beta  = (const float*)d_in[4];
    const float* W_dkv   = (const float*)d_in[5];
    const float* W_ukv   = (const float*)d_in[6];
    const float* kv_gamma= (const float*)d_in[7];
    const float* kv_beta = (const float*)d_in[8];
    const float* W_o     = (const float*)d_in[9];

    float* out = (float*)d_out;
    float* ckv = out + OUT_HALF;

    float *t0, *Qp, *KVp;
    cudaGetSymbolAddress((void**)&t0,  g_t0);
    cudaGetSymbolAddress((void**)&Qp,  g_Q);
    cudaGetSymbolAddress((void**)&KVp, g_KV);
    bf16 *xh,*xl,*cqh,*cql,*ckvh,*ckvl,*Oph,*Opl;
    bf16 *wdqh,*wdql,*wdkvh,*wdkvl,*wuqh,*wuql,*wukvh,*wukvl,*woh,*wol;
    cudaGetSymbolAddress((void**)&xh,  g_xh);   cudaGetSymbolAddress((void**)&xl,  g_xl);
    cudaGetSymbolAddress((void**)&cqh, g_cqh);  cudaGetSymbolAddress((void**)&cql, g_cql);
    cudaGetSymbolAddress((void**)&ckvh,g_ckvh); cudaGetSymbolAddress((void**)&ckvl,g_ckvl);
    cudaGetSymbolAddress((void**)&Oph, g_Oh);   cudaGetSymbolAddress((void**)&Opl, g_Ol);
    cudaGetSymbolAddress((void**)&wdqh, g_Wdqh);  cudaGetSymbolAddress((void**)&wdql, g_Wdql);
    cudaGetSymbolAddress((void**)&wdkvh,g_Wdkvh); cudaGetSymbolAddress((void**)&wdkvl,g_Wdkvl);
    cudaGetSymbolAddress((void**)&wuqh, g_Wuqh);  cudaGetSymbolAddress((void**)&wuql, g_Wuql);
    cudaGetSymbolAddress((void**)&wukvh,g_Wukvh); cudaGetSymbolAddress((void**)&wukvl,g_Wukvl);
    cudaGetSymbolAddress((void**)&woh,  g_Woh);   cudaGetSymbolAddress((void**)&wol,  g_Wol);

    cudaFuncSetAttribute(gemm_mma, cudaFuncAttributeMaxDynamicSharedMemorySize, GEMM_SMEM);

    const int D = D_MODEL;
    const dim3 tsB(32, 8);

    // operand preparation
    split_f32<<<(ROWS * D / 4 + 255) / 256, 256>>>(x, xh, xl, ROWS * D / 4);
    tsplit<<<dim3(D / 32, D / 32), tsB>>>(W_dq,  wdqh,  wdql,  D, D);
    tsplit<<<dim3(D / 32, D / 32), tsB>>>(W_dkv, wdkvh, wdkvl, D, D);
    tsplit<<<dim3(D / 32, D / 32), tsB>>>(W_uq,  wuqh,  wuql,  D, D);
    tsplit<<<dim3(2 * D / 32, D / 32), tsB>>>(W_ukv, wukvh, wukvl, D, 2 * D);
    split_f32<<<(D * D / 4 + 255) / 256, 256>>>(W_o, woh, wol, D * D / 4);  // already [N,K]
    rope_table<<<SEQ, DH / 2>>>();

    const dim3 gN(D / 128, ROWS / 128);          // (16, 32)
    const dim3 gKV(2 * D / 128, ROWS / 128);     // (32, 32)

    // Q path
    gemm_mma<<<gN, 256, GEMM_SMEM>>>(xh, xl, wdqh, wdql, t0, D, D);
    layernorm_split<<<ROWS, 256>>>(t0, q_gamma, q_beta, nullptr, cqh, cql);
    // KV path (ckv fp32 straight into d_out)
    gemm_mma<<<gN, 256, GEMM_SMEM>>>(xh, xl, wdkvh, wdkvl, t0, D, D);
    layernorm_split<<<ROWS, 256>>>(t0, kv_gamma, kv_beta, ckv, ckvh, ckvl);
    // up-projections
    gemm_mma<<<gN, 256, GEMM_SMEM>>>(cqh, cql, wuqh, wuql, Qp, D, D);
    gemm_mma<<<gKV, 256, GEMM_SMEM>>>(ckvh, ckvl, wukvh, wukvl, KVp, 2 * D, D);
    // RoPE + attention
    rope_apply<<<ROWS, 256>>>(Qp, KVp);
    flash_attn<<<dim3(SEQ / BR, BATCH * NHEADS), 256>>>(Qp, KVp, Oph, Opl);
    // out = O @ W_o^T
    gemm_mma<<<gN, 256, GEMM_SMEM>>>(Oph, Opl, woh, wol, out, D, D);
}

// round 4
// speedup vs baseline: 6.1226x; 4.6186x over previous
#include <cuda_runtime.h>
#include <cuda_bf16.h>
#include <math.h>
#include <stdint.h>

// ---------------------------------------------------------------------------
// MLA prefill, Round 4: mma.sync bf16x3 GEMMs + mma.sync flash attention
//   B=2, S=2048, D=2048, H=16, dh=128
// ---------------------------------------------------------------------------

#define D_MODEL 2048
#define SEQ     2048
#define BATCH   2
#define NHEADS  16
#define DH      128
#define ROWS    (BATCH * SEQ)               // 4096
#define OUT_HALF ((size_t)ROWS * D_MODEL)

typedef __nv_bfloat16 bf16;

// ----------------------------- static scratch -------------------------------
__device__ float g_t0[(size_t)ROWS * D_MODEL];
__device__ float g_Q [(size_t)ROWS * D_MODEL];
__device__ float g_KV[(size_t)ROWS * 2 * D_MODEL];
__device__ float g_cos[SEQ][DH / 2];
__device__ float g_sin[SEQ][DH / 2];

__device__ bf16 g_xh [(size_t)ROWS * D_MODEL], g_xl [(size_t)ROWS * D_MODEL];
__device__ bf16 g_cqh[(size_t)ROWS * D_MODEL], g_cql[(size_t)ROWS * D_MODEL];
__device__ bf16 g_ckvh[(size_t)ROWS * D_MODEL], g_ckvl[(size_t)ROWS * D_MODEL];
__device__ bf16 g_Oh [(size_t)ROWS * D_MODEL], g_Ol [(size_t)ROWS * D_MODEL];
// attention operands: Q/K [B*H, S, 128]; V transposed [B*H, 128, S]
__device__ bf16 g_Qh[(size_t)ROWS * D_MODEL], g_Ql[(size_t)ROWS * D_MODEL];
__device__ bf16 g_Kh[(size_t)ROWS * D_MODEL], g_Kl[(size_t)ROWS * D_MODEL];
__device__ bf16 g_Vh[(size_t)ROWS * D_MODEL], g_Vl[(size_t)ROWS * D_MODEL];

__device__ bf16 g_Wdqh [(size_t)D_MODEL * D_MODEL], g_Wdql [(size_t)D_MODEL * D_MODEL];
__device__ bf16 g_Wdkvh[(size_t)D_MODEL * D_MODEL], g_Wdkvl[(size_t)D_MODEL * D_MODEL];
__device__ bf16 g_Wuqh [(size_t)D_MODEL * D_MODEL], g_Wuql [(size_t)D_MODEL * D_MODEL];
__device__ bf16 g_Wukvh[(size_t)2 * D_MODEL * D_MODEL], g_Wukvl[(size_t)2 * D_MODEL * D_MODEL];
__device__ bf16 g_Woh  [(size_t)D_MODEL * D_MODEL], g_Wol  [(size_t)D_MODEL * D_MODEL];

// ----------------------------- PTX helpers -----------------------------------
__device__ __forceinline__ uint32_t smem_u32(const void* p) {
    uint32_t a;
    asm("{ .reg .u64 t; cvta.to.shared.u64 t, %1; cvt.u32.u64 %0, t; }" : "=r"(a) : "l"(p));
    return a;
}
#define CP_ASYNC16(sa, ga) \
    asm volatile("cp.async.cg.shared.global [%0], [%1], 16;" :: "r"(sa), "l"(ga))
#define CP_COMMIT() asm volatile("cp.async.commit_group;" ::: "memory")
#define CP_WAIT1()  asm volatile("cp.async.wait_group 1;" ::: "memory")
#define CP_WAIT0()  asm volatile("cp.async.wait_group 0;" ::: "memory")
#define LDSM4(r, a) \
    asm volatile("ldmatrix.sync.aligned.m8n8.x4.shared.b16 {%0,%1,%2,%3}, [%4];" \
        : "=r"((r)[0]), "=r"((r)[1]), "=r"((r)[2]), "=r"((r)[3]) : "r"(a))
#define MMA16816(c, a, b) \
    asm volatile("mma.sync.aligned.m16n8k16.row.col.f32.bf16.bf16.f32 " \
        "{%0,%1,%2,%3}, {%4,%5,%6,%7}, {%8,%9}, {%0,%1,%2,%3};" \
        : "+f"((c)[0]), "+f"((c)[1]), "+f"((c)[2]), "+f"((c)[3]) \
        : "r"((a)[0]), "r"((a)[1]), "r"((a)[2]), "r"((a)[3]), "r"((b)[0]), "r"((b)[1]))

__device__ __forceinline__ float ex2f(float x) {
    float y; asm("ex2.approx.ftz.f32 %0, %1;" : "=f"(y) : "f"(x)); return y;
}
__device__ __forceinline__ uint32_t packbf(float lo, float hi) {
    __nv_bfloat162 t = __floats2bfloat162_rn(lo, hi);
    return *reinterpret_cast<uint32_t*>(&t);
}

// ----------------------------- split kernels ---------------------------------
__global__ __launch_bounds__(256) void split_f32(const float* __restrict__ in,
                                                 bf16* __restrict__ oh, bf16* __restrict__ ol,
                                                 int n4)
{
    int i = blockIdx.x * 256 + threadIdx.x;
    if (i >= n4) return;
    float4 v = reinterpret_cast<const float4*>(in)[i];
    bf16 h0 = __float2bfloat16(v.x), h1 = __float2bfloat16(v.y);
    bf16 h2 = __float2bfloat16(v.z), h3 = __float2bfloat16(v.w);
    reinterpret_cast<__nv_bfloat162*>(oh)[i * 2]     = __halves2bfloat162(h0, h1);
    reinterpret_cast<__nv_bfloat162*>(oh)[i * 2 + 1] = __halves2bfloat162(h2, h3);
    reinterpret_cast<__nv_bfloat162*>(ol)[i * 2] = __halves2bfloat162(
        __float2bfloat16(v.x - __bfloat162float(h0)),
        __float2bfloat16(v.y - __bfloat162float(h1)));
    reinterpret_cast<__nv_bfloat162*>(ol)[i * 2 + 1] = __halves2bfloat162(
        __float2bfloat16(v.z - __bfloat162float(h2)),
        __float2bfloat16(v.w - __bfloat162float(h3)));
}

__global__ __launch_bounds__(256) void tsplit(const float* __restrict__ W,
                                              bf16* __restrict__ oh, bf16* __restrict__ ol,
                                              int K, int N)
{
    __shared__ float t[32][33];
    const int tx = threadIdx.x, ty = threadIdx.y;
    const int n0 = blockIdx.x * 32, k0 = blockIdx.y * 32;
#pragma unroll
    for (int i = 0; i < 4; i++)
        t[ty + i * 8][tx] = W[(size_t)(k0 + ty + i * 8) * N + n0 + tx];
    __syncthreads();
#pragma unroll
    for (int i = 0; i < 4; i++) {
        float v = t[tx][ty + i * 8];
        int n = n0 + ty + i * 8, k = k0 + tx;
        bf16 h = __float2bfloat16(v);
        oh[(size_t)n * K + k] = h;
        ol[(size_t)n * K + k] = __float2bfloat16(v - __bfloat162float(h));
    }
}

// ----------------------------- mma.sync GEMM (unchanged, validated) ----------
#define GEMM_SMEM 65536

__global__ __launch_bounds__(256) void gemm_mma(
    const bf16* __restrict__ Ah, const bf16* __restrict__ Al,
    const bf16* __restrict__ Bh, const bf16* __restrict__ Bl,
    float* __restrict__ C, int N, int K)
{
    extern __shared__ char sm[];
    const uint32_t smb = smem_u32(sm);
    const int tid  = threadIdx.x;
    const int lane = tid & 31, wid = tid >> 5;
    const int wm = wid & 3, wn = wid >> 2;
    const size_t aB = (size_t)blockIdx.y * 128 * K;
    const size_t bB = (size_t)blockIdx.x * 128 * K;

    float acc[2][8][4];
#pragma unroll
    for (int i = 0; i < 2; i++)
#pragma unroll
        for (int j = 0; j < 8; j++)
#pragma unroll
            for (int t = 0; t < 4; t++) acc[i][j][t] = 0.f;

    auto load_stage = [&](int s, int k0) {
        const uint32_t sb = smb + s * 32768;
#pragma unroll
        for (int h = 0; h < 2; h++) {
            const int c  = tid + h * 256;
            const int r  = c >> 2, ch = c & 3;
            const uint32_t off = r * 64 + ((ch ^ ((r >> 1) & 3)) << 4);
            const size_t g = (size_t)r * K + k0 + ch * 8;
            CP_ASYNC16(sb + off,         Ah + aB + g);
            CP_ASYNC16(sb + 8192  + off, Al + aB + g);
            CP_ASYNC16(sb + 16384 + off, Bh + bB + g);
            CP_ASYNC16(sb + 24576 + off, Bl + bB + g);
        }
    };

    auto compute_stage = [&](int s) {
        const uint32_t sb = smb + s * 32768;
#pragma unroll
        for (int kk = 0; kk < 2; kk++) {
            uint32_t ah[2][4], al[2][4];
#pragma unroll
            for (int mt = 0; mt < 2; mt++) {
                const int r     = wm * 32 + mt * 16 + (lane & 15);
                const int chunk = kk * 2 + (lane >> 4);
                const uint32_t off = r * 64 + ((chunk ^ ((r >> 1) & 3)) << 4);
                LDSM4(ah[mt], sb + off);
                LDSM4(al[mt], sb + 8192 + off);
            }
#pragma unroll
            for (int np = 0; np < 4; np++) {
                const int r     = wn * 64 + np * 16 + (lane & 15);
                const int chunk = kk * 2 + (lane >> 4);
                const uint32_t off = r * 64 + ((chunk ^ ((r >> 1) & 3)) << 4);
                uint32_t b4h[4], b4l[4];
                LDSM4(b4h, sb + 16384 + off);
                LDSM4(b4l, sb + 24576 + off);
#pragma unroll
                for (int j = 0; j < 2; j++) {
                    const int nt = np * 2 + j;
                    uint32_t bh2[2] = { b4h[j], b4h[j + 2] };
                    uint32_t bl2[2] = { b4l[j], b4l[j + 2] };
                    MMA16816(acc[0][nt], ah[0], bh2);
                    MMA16816(acc[1][nt], ah[1], bh2);
                    MMA16816(acc[0][nt], ah[0], bl2);
                    MMA16816(acc[1][nt], ah[1], bl2);
                    MMA16816(acc[0][nt], al[0], bh2);
                    MMA16816(acc[1][nt], al[1], bh2);
                }
            }
        }
    };

    load_stage(0, 0);  CP_COMMIT();
    load_stage(1, 32); CP_COMMIT();
    const int iters = K >> 5;
    for (int it = 0; it < iters; it++) {
        const int s = it & 1;
        CP_WAIT1();
        __syncthreads();
        compute_stage(s);
        __syncthreads();
        const int kn = (it + 2) << 5;
        if (kn < K) load_stage(s, kn);
        CP_COMMIT();
    }
    CP_WAIT0();

#pragma unroll
    for (int mt = 0; mt < 2; mt++) {
        const int m0 = blockIdx.y * 128 + wm * 32 + mt * 16 + (lane >> 2);
#pragma unroll
        for (int nt = 0; nt < 8; nt++) {
            const int n = blockIdx.x * 128 + wn * 64 + nt * 8 + (lane & 3) * 2;
            *(float2*)(C + (size_t)m0 * N + n)       = make_float2(acc[mt][nt][0], acc[mt][nt][1]);
            *(float2*)(C + (size_t)(m0 + 8) * N + n) = make_float2(acc[mt][nt][2], acc[mt][nt][3]);
        }
    }
}

// ----------------------------- LayerNorm + split -----------------------------
__global__ __launch_bounds__(256) void layernorm_split(
    const float* __restrict__ in, const float* __restrict__ gamma,
    const float* __restrict__ beta, float* __restrict__ of,
    bf16* __restrict__ oh, bf16* __restrict__ ol)
{
    __shared__ float red[16];
    const int row = blockIdx.x;
    const float* x = in + (size_t)row * D_MODEL;
    float s = 0.f, s2 = 0.f;
    for (int i = threadIdx.x; i < D_MODEL; i += 256) {
        float v = x[i]; s += v; s2 += v * v;
    }
#pragma unroll
    for (int o = 16; o; o >>= 1) {
        s  += __shfl_xor_sync(0xffffffffu, s,  o);
        s2 += __shfl_xor_sync(0xffffffffu, s2, o);
    }
    const int wid = threadIdx.x >> 5, lane = threadIdx.x & 31;
    if (lane == 0) { red[wid] = s; red[wid + 8] = s2; }
    __syncthreads();
    if (threadIdx.x < 32) {
        s  = (lane < 8) ? red[lane]     : 0.f;
        s2 = (lane < 8) ? red[lane + 8] : 0.f;
#pragma unroll
        for (int o = 4; o; o >>= 1) {
            s  += __shfl_xor_sync(0xffffffffu, s,  o);
            s2 += __shfl_xor_sync(0xffffffffu, s2, o);
        }
        if (lane == 0) { red[0] = s; red[1] = s2; }
    }
    __syncthreads();
    const float mean = red[0] * (1.f / D_MODEL);
    const float var  = red[1] * (1.f / D_MODEL) - mean * mean;
    const float rstd = rsqrtf(var + 1e-5f);
    for (int i = threadIdx.x; i < D_MODEL; i += 256) {
        const float v = (x[i] - mean) * rstd * gamma[i] + beta[i];
        if (of) of[(size_t)row * D_MODEL + i] = v;
        const bf16 h = __float2bfloat16(v);
        oh[(size_t)row * D_MODEL + i] = h;
        ol[(size_t)row * D_MODEL + i] = __float2bfloat16(v - __bfloat162float(h));
    }
}

// ----------------------------- RoPE ------------------------------------------
__global__ void rope_table()
{
    const int s = blockIdx.x, i = threadIdx.x;
    const double freq = pow(10000.0, -2.0 * (double)i / (double)DH);
    const double a = (double)s * freq;
    g_cos[s][i] = (float)cos(a);
    g_sin[s][i] = (float)sin(a);
}

// RoPE + split + relayout for tensor-core attention.
// Q scaled by softmax_scale*log2(e), split -> [bh][S][128]
// K rope, split -> [bh][S][128].  V split, TRANSPOSED -> [bh][128][S]
__global__ __launch_bounds__(256) void rope_split(
    const float* __restrict__ Q, const float* __restrict__ KV,
    bf16* __restrict__ Qh, bf16* __restrict__ Ql,
    bf16* __restrict__ Kh, bf16* __restrict__ Kl,
    bf16* __restrict__ Vh, bf16* __restrict__ Vl)
{
    const float QSCALE = 0.08838834764831845f * 1.4426950408889634f;
    const int row = blockIdx.x;
    const int b = row / SEQ, s = row & (SEQ - 1);
    for (int p = threadIdx.x; p < NHEADS * (DH / 2); p += 256) {
        const int h = p >> 6, i = p & 63;
        const int bh = b * NHEADS + h;
        const float cs = g_cos[s][i], sn = g_sin[s][i];
        // Q
        {
            const size_t src = (size_t)row * D_MODEL + h * DH;
            float x1 = Q[src + i], x2 = Q[src + 64 + i];
            float r1 = (x1 * cs - x2 * sn) * QSCALE;
            float r2 = (x2 * cs + x1 * sn) * QSCALE;
            const size_t dst = ((size_t)bh * SEQ + s) * DH;
            bf16 h1 = __float2bfloat16(r1), h2 = __float2bfloat16(r2);
            Qh[dst + i] = h1;       Qh[dst + 64 + i] = h2;
            Ql[dst + i] = __float2bfloat16(r1 - __bfloat162float(h1));
            Ql[dst + 64 + i] = __float2bfloat16(r2 - __bfloat162float(h2));
        }
        // K
        {
            const size_t src = (size_t)row * 2 * D_MODEL + h * DH;
            float x1 = KV[src + i], x2 = KV[src + 64 + i];
            float r1 = x1 * cs - x2 * sn;
            float r2 = x2 * cs + x1 * sn;
            const size_t dst = ((size_t)bh * SEQ + s) * DH;
            bf16 h1 = __float2bfloat16(r1), h2 = __float2bfloat16(r2);
            Kh[dst + i] = h1;       Kh[dst + 64 + i] = h2;
            Kl[dst + i] = __float2bfloat16(r1 - __bfloat162float(h1));
            Kl[dst + 64 + i] = __float2bfloat16(r2 - __bfloat162float(h2));
        }
        // V (transposed store)
        {
            const size_t src = (size_t)row * 2 * D_MODEL + D_MODEL + h * DH;
            float v1 = KV[src + i], v2 = KV[src + 64 + i];
            bf16 h1 = __float2bfloat16(v1), h2 = __float2bfloat16(v2);
            const size_t d1 = ((size_t)bh * DH + i) * SEQ + s;
            const size_t d2 = ((size_t)bh * DH + 64 + i) * SEQ + s;
            Vh[d1] = h1; Vh[d2] = h2;
            Vl[d1] = __float2bfloat16(v1 - __bfloat162float(h1));
            Vl[d2] = __float2bfloat16(v2 - __bfloat162float(h2));
        }
    }
}

// ----------------------------- tensor-core flash attention -------------------
// CTA: 64 queries x one (b,h). 4 warps x m16. 64-key tiles.
// smem: Qh/Ql/Kh/Kl [64 rows x 256B pad 272B], Vh/Vl^T [128 rows x 128B pad 144B]
#define QK_STR 272
#define V_STR  144
#define A_QH 0
#define A_QL 17408
#define A_KH 34816
#define A_KL 52224
#define A_VH 69632
#define A_VL 88064
#define ATT_SMEM 106496

__global__ __launch_bounds__(128) void flash_attn_mma(
    const bf16* __restrict__ Qh, const bf16* __restrict__ Ql,
    const bf16* __restrict__ Kh, const bf16* __restrict__ Kl,
    const bf16* __restrict__ Vh, const bf16* __restrict__ Vl,
    bf16* __restrict__ Oh, bf16* __restrict__ Ol)
{
    extern __shared__ __align__(16) char sm[];
    const uint32_t smb = smem_u32(sm);
    const int tid  = threadIdx.x;
    const int lane = tid & 31, wid = tid >> 5;
    const int qb = (int)(gridDim.x - 1 - blockIdx.x);     // longest first
    const int bh = blockIdx.y;
    const int b  = bh >> 4, h = bh & 15;

    const size_t qkBase = (size_t)bh * SEQ * DH;
    const size_t vBase  = (size_t)bh * DH * SEQ;

    // ---- load Q tile (once) ----
#pragma unroll
    for (int j = 0; j < 8; j++) {
        const int c = j * 128 + tid;          // 0..1023
        const int r = c >> 4, col = c & 15;
        const uint32_t off = r * QK_STR + col * 16;
        const size_t g = qkBase + (size_t)(qb * 64 + r) * DH + col * 8;
        CP_ASYNC16(smb + A_QH + off, Qh + g);
        CP_ASYNC16(smb + A_QL + off, Ql + g);
    }
    // ---- load K/V tile 0 ----
    auto load_kv = [&](int kt) {
#pragma unroll
        for (int j = 0; j < 8; j++) {
            const int c = j * 128 + tid;
            const int r = c >> 4, col = c & 15;
            const uint32_t off = r * QK_STR + col * 16;
            const size_t g = qkBase + (size_t)(kt * 64 + r) * DH + col * 8;
            CP_ASYNC16(smb + A_KH + off, Kh + g);
            CP_ASYNC16(smb + A_KL + off, Kl + g);
        }
#pragma unroll
        for (int j = 0; j < 8; j++) {
            const int c = j * 128 + tid;
            const int r = c >> 3, col = c & 7;
            const uint32_t off = r * V_STR + col * 16;
            const size_t g = vBase + (size_t)r * SEQ + kt * 64 + col * 8;
            CP_ASYNC16(smb + A_VH + off, Vh + g);
            CP_ASYNC16(smb + A_VL + off, Vl + g);
        }
    };
    load_kv(0);
    CP_COMMIT();
    CP_WAIT0();
    __syncthreads();

    float o[16][4];
#pragma unroll
    for (int t = 0; t < 16; t++)
#pragma unroll
        for (int k = 0; k < 4; k++) o[t][k] = 0.f;
    float m0 = -1e30f, m1 = -1e30f, l0 = 0.f, l1 = 0.f;

    const int mrow = wid * 16;
    const int ktiles = qb + 1;

    for (int kt = 0; kt < ktiles; kt++) {
        // ---- scores: c[8][4] = Q . K^T (bf16x3) ----
        float c[8][4];
#pragma unroll
        for (int j = 0; j < 8; j++)
#pragma unroll
            for (int k = 0; k < 4; k++) c[j][k] = 0.f;

#pragma unroll
        for (int kc = 0; kc < 8; kc++) {
            const uint32_t aoff = (mrow + (lane & 15)) * QK_STR + (kc * 2 + (lane >> 4)) * 16;
            uint32_t qh4[4], ql4[4];
            LDSM4(qh4, smb + A_QH + aoff);
            LDSM4(ql4, smb + A_QL + aoff);
#pragma unroll
            for (int jj = 0; jj < 4; jj++) {
                const uint32_t boff = (jj * 16 + (lane & 15)) * QK_STR + (kc * 2 + (lane >> 4)) * 16;
                uint32_t kh4[4], kl4[4];
                LDSM4(kh4, smb + A_KH + boff);
                LDSM4(kl4, smb + A_KL + boff);
#pragma unroll
                for (int t = 0; t < 2; t++) {
                    const int j = jj * 2 + t;
                    uint32_t bh2[2] = { kh4[t], kh4[t + 2] };
                    uint32_t bl2[2] = { kl4[t], kl4[t + 2] };
                    MMA16816(c[j], qh4, bh2);
                    MMA16816(c[j], qh4, bl2);
                    MMA16816(c[j], ql4, bh2);
                }
            }
        }

        // ---- causal mask on the diagonal tile ----
        if (kt == qb) {
            const int rlo = mrow + (lane >> 2);
#pragma unroll
            for (int j = 0; j < 8; j++) {
                const int cb = j * 8 + (lane & 3) * 2;
                if (cb     > rlo)     c[j][0] = -1e30f;
                if (cb + 1 > rlo)     c[j][1] = -1e30f;
                if (cb     > rlo + 8) c[j][2] = -1e30f;
                if (cb + 1 > rlo + 8) c[j][3] = -1e30f;
            }
        }

        // ---- online softmax (base-2; scale folded into Q) ----
        float tm0 = c[0][0], tm1 = c[0][2];
#pragma unroll
        for (int j = 0; j < 8; j++) {
            tm0 = fmaxf(tm0, fmaxf(c[j][0], c[j][1]));
            tm1 = fmaxf(tm1, fmaxf(c[j][2], c[j][3]));
        }
        tm0 = fmaxf(tm0, __shfl_xor_sync(0xffffffffu, tm0, 1));
        tm0 = fmaxf(tm0, __shfl_xor_sync(0xffffffffu, tm0, 2));
        tm1 = fmaxf(tm1, __shfl_xor_sync(0xffffffffu, tm1, 1));
        tm1 = fmaxf(tm1, __shfl_xor_sync(0xffffffffu, tm1, 2));
        const float mn0 = fmaxf(m0, tm0), mn1 = fmaxf(m1, tm1);
        const float al0 = ex2f(m0 - mn0), al1 = ex2f(m1 - mn1);
        m0 = mn0; m1 = mn1;
        float s0 = 0.f, s1 = 0.f;
#pragma unroll
        for (int j = 0; j < 8; j++) {
            c[j][0] = ex2f(c[j][0] - mn0); s0 += c[j][0];
            c[j][1] = ex2f(c[j][1] - mn0); s0 += c[j][1];
            c[j][2] = ex2f(c[j][2] - mn1); s1 += c[j][2];
            c[j][3] = ex2f(c[j][3] - mn1); s1 += c[j][3];
        }
        s0 += __shfl_xor_sync(0xffffffffu, s0, 1);
        s0 += __shfl_xor_sync(0xffffffffu, s0, 2);
        s1 += __shfl_xor_sync(0xffffffffu, s1, 1);
        s1 += __shfl_xor_sync(0xffffffffu, s1, 2);
        l0 = l0 * al0 + s0;
        l1 = l1 * al1 + s1;
#pragma unroll
        for (int t = 0; t < 16; t++) {
            o[t][0] *= al0; o[t][1] *= al0;
            o[t][2] *= al1; o[t][3] *= al1;
        }

        // ---- P -> bf16 h/l A-fragments ----
        uint32_t ph[4][4], pl[4][4];
#pragma unroll
        for (int kc = 0; kc < 4; kc++) {
            const int j0 = kc * 2, j1 = kc * 2 + 1;
            float r00 = c[j0][0], r01 = c[j0][1], r02 = c[j0][2], r03 = c[j0][3];
            float r10 = c[j1][0], r11 = c[j1][1], r12 = c[j1][2], r13 = c[j1][3];
            float h00 = __bfloat162float(__float2bfloat16(r00));
            float h01 = __bfloat162float(__float2bfloat16(r01));
            float h02 = __bfloat162float(__float2bfloat16(r02));
            float h03 = __bfloat162float(__float2bfloat16(r03));
            float h10 = __bfloat162float(__float2bfloat16(r10));
            float h11 = __bfloat162float(__float2bfloat16(r11));
            float h12 = __bfloat162float(__float2bfloat16(r12));
            float h13 = __bfloat162float(__float2bfloat16(r13));
            ph[kc][0] = packbf(h00, h01); ph[kc][1] = packbf(h02, h03);
            ph[kc][2] = packbf(h10, h11); ph[kc][3] = packbf(h12, h13);
            pl[kc][0] = packbf(r00 - h00, r01 - h01);
            pl[kc][1] = packbf(r02 - h02, r03 - h03);
            pl[kc][2] = packbf(r10 - h10, r11 - h11);
            pl[kc][3] = packbf(r12 - h12, r13 - h13);
        }

        // ---- O += P . V  (Ph.Vh + Pl.Vh + Ph.Vl) ----
#pragma unroll
        for (int kc = 0; kc < 4; kc++) {
#pragma unroll
            for (int g = 0; g < 8; g++) {
                const uint32_t voff = (g * 16 + (lane & 15)) * V_STR + (kc * 2 + (lane >> 4)) * 16;
                uint32_t vh4[4], vl4[4];
                LDSM4(vh4, smb + A_VH + voff);
                LDSM4(vl4, smb + A_VL + voff);
#pragma unroll
                for (int t = 0; t < 2; t++) {
                    const int nt = g * 2 + t;
                    uint32_t bh2[2] = { vh4[t], vh4[t + 2] };
                    uint32_t bl2[2] = { vl4[t], vl4[t + 2] };
                    MMA16816(o[nt], ph[kc], bh2);
                    MMA16816(o[nt], pl[kc], bh2);
                    MMA16816(o[nt], ph[kc], bl2);
                }
            }
        }

        // ---- next K/V tile ----
        if (kt < qb) {
            __syncthreads();
            load_kv(kt + 1);
            CP_COMMIT();
            CP_WAIT0();
            __syncthreads();
        }
    }

    // ---- epilogue: normalize, split to bf16 h/l, store [row][D] ----
    const float inv0 = 1.f / l0, inv1 = 1.f / l1;
    const int r0 = qb * 64 + mrow + (lane >> 2);
    const size_t rowA = ((size_t)(b * SEQ) + r0) * D_MODEL + h * DH;
    const size_t rowB = rowA + 8 * D_MODEL;
#pragma unroll
    for (int t = 0; t < 16; t++) {
        const int col = t * 8 + (lane & 3) * 2;
        float v0 = o[t][0] * inv0, v1 = o[t][1] * inv0;
        float v2 = o[t][2] * inv1, v3 = o[t][3] * inv1;
        float h0 = __bfloat162float(__float2bfloat16(v0));
        float h1 = __bfloat162float(__float2bfloat16(v1));
        float h2 = __bfloat162float(__float2bfloat16(v2));
        float h3 = __bfloat162float(__float2bfloat16(v3));
        *(uint32_t*)(Oh + rowA + col) = packbf(h0, h1);
        *(uint32_t*)(Oh + rowB + col) = packbf(h2, h3);
        *(uint32_t*)(Ol + rowA + col) = packbf(v0 - h0, v1 - h1);
        *(uint32_t*)(Ol + rowB + col) = packbf(v2 - h2, v3 - h3);
    }
}

// ----------------------------- launch ----------------------------------------
extern "C" void kernel_launch(void* const* d_in, const int* in_sizes, int n_in,
                              void* d_out, int out_size)
{
    const float* x       = (const float*)d_in[0];
    const float* W_dq    = (const float*)d_in[1];
    const float* W_uq    = (const float*)d_in[2];
    const float* q_gamma = (const float*)d_in[3];
    const float* q_beta  = (const float*)d_in[4];
    const float* W_dkv   = (const float*)d_in[5];
    const float* W_ukv   = (const float*)d_in[6];
    const float* kv_gamma= (const float*)d_in[7];
    const float* kv_beta = (const float*)d_in[8];
    const float* W_o     = (const float*)d_in[9];

    float* out = (float*)d_out;
    float* ckv = out + OUT_HALF;

    float *t0, *Qp, *KVp;
    cudaGetSymbolAddress((void**)&t0,  g_t0);
    cudaGetSymbolAddress((void**)&Qp,  g_Q);
    cudaGetSymbolAddress((void**)&KVp, g_KV);
    bf16 *xh,*xl,*cqh,*cql,*ckvh,*ckvl,*Oph,*Opl;
    bf16 *qh,*ql,*kh,*kl,*vh,*vl;
    bf16 *wdqh,*wdql,*wdkvh,*wdkvl,*wuqh,*wuql,*wukvh,*wukvl,*woh,*wol;
    cudaGetSymbolAddress((void**)&xh,  g_xh);   cudaGetSymbolAddress((void**)&xl,  g_xl);
    cudaGetSymbolAddress((void**)&cqh, g_cqh);  cudaGetSymbolAddress((void**)&cql, g_cql);
    cudaGetSymbolAddress((void**)&ckvh,g_ckvh); cudaGetSymbolAddress((void**)&ckvl,g_ckvl);
    cudaGetSymbolAddress((void**)&Oph, g_Oh);   cudaGetSymbolAddress((void**)&Opl, g_Ol);
    cudaGetSymbolAddress((void**)&qh,  g_Qh);   cudaGetSymbolAddress((void**)&ql,  g_Ql);
    cudaGetSymbolAddress((void**)&kh,  g_Kh);   cudaGetSymbolAddress((void**)&kl,  g_Kl);
    cudaGetSymbolAddress((void**)&vh,  g_Vh);   cudaGetSymbolAddress((void**)&vl,  g_Vl);
    cudaGetSymbolAddress((void**)&wdqh, g_Wdqh);  cudaGetSymbolAddress((void**)&wdql, g_Wdql);
    cudaGetSymbolAddress((void**)&wdkvh,g_Wdkvh); cudaGetSymbolAddress((void**)&wdkvl,g_Wdkvl);
    cudaGetSymbolAddress((void**)&wuqh, g_Wuqh);  cudaGetSymbolAddress((void**)&wuql, g_Wuql);
    cudaGetSymbolAddress((void**)&wukvh,g_Wukvh); cudaGetSymbolAddress((void**)&wukvl,g_Wukvl);
    cudaGetSymbolAddress((void**)&woh,  g_Woh);   cudaGetSymbolAddress((void**)&wol,  g_Wol);

    cudaFuncSetAttribute(gemm_mma, cudaFuncAttributeMaxDynamicSharedMemorySize, GEMM_SMEM);
    cudaFuncSetAttribute(flash_attn_mma, cudaFuncAttributeMaxDynamicSharedMemorySize, ATT_SMEM);

    const int D = D_MODEL;
    const dim3 tsB(32, 8);

    // operand preparation
    split_f32<<<(ROWS * D / 4 + 255) / 256, 256>>>(x, xh, xl, ROWS * D / 4);
    tsplit<<<dim3(D / 32, D / 32), tsB>>>(W_dq,  wdqh,  wdql,  D, D);
    tsplit<<<dim3(D / 32, D / 32), tsB>>>(W_dkv, wdkvh, wdkvl, D, D);
    tsplit<<<dim3(D / 32, D / 32), tsB>>>(W_uq,  wuqh,  wuql,  D, D);
    tsplit<<<dim3(2 * D / 32, D / 32), tsB>>>(W_ukv, wukvh, wukvl, D, 2 * D);
    split_f32<<<(D * D / 4 + 255) / 256, 256>>>(W_o, woh, wol, D * D / 4);
    rope_table<<<SEQ, DH / 2>>>();

    const dim3 gN(D / 128, ROWS / 128);
    const dim3 gKV(2 * D / 128, ROWS / 128);

    // Q path
    gemm_mma<<<gN, 256, GEMM_SMEM>>>(xh, xl, wdqh, wdql, t0, D, D);
    layernorm_split<<<ROWS, 256>>>(t0, q_gamma, q_beta, nullptr, cqh, cql);
    // KV path (ckv fp32 straight into d_out)
    gemm_mma<<<gN, 256, GEMM_SMEM>>>(xh, xl, wdkvh, wdkvl, t0, D, D);
    layernorm_split<<<ROWS, 256>>>(t0, kv_gamma, kv_beta, ckv, ckvh, ckvl);
    // up-projections
    gemm_mma<<<gN, 256, GEMM_SMEM>>>(cqh, cql, wuqh, wuql, Qp, D, D);
    gemm_mma<<<gKV, 256, GEMM_SMEM>>>(ckvh, ckvl, wukvh, wukvl, KVp, 2 * D, D);
    // RoPE + split + relayout
    rope_split<<<ROWS, 256>>>(Qp, KVp, qh, ql, kh, kl, vh, vl);
    // tensor-core causal attention
    flash_attn_mma<<<dim3(SEQ / 64, BATCH * NHEADS), 128, ATT_SMEM>>>(
        qh, ql, kh, kl, vh, vl, Oph, Opl);
    // out = O @ W_o^T
    gemm_mma<<<gN, 256, GEMM_SMEM>>>(Oph, Opl, woh, wol, out, D, D);
}